// round 4
// baseline (speedup 1.0000x reference)
#include <cuda_runtime.h>
#include <cuda_bf16.h>
#include <cstdint>
#include <math.h>

#define BB 4
#define SS 2048
#define DD 1024
#define BSR (BB * SS)
#define SCALE (1.0f / 32.0f)

// ---------------------------------------------------------------------------
// Scratch (__device__ globals; no allocation allowed)
// ---------------------------------------------------------------------------
__device__ __align__(128) __nv_bfloat16 g_x_hi[BSR * DD], g_x_lo[BSR * DD];
__device__ __align__(128) __nv_bfloat16 g_Wt_hi[3 * DD * DD], g_Wt_lo[3 * DD * DD];
__device__ __align__(128) __nv_bfloat16 g_Q_hi[BSR * DD], g_Q_lo[BSR * DD];
__device__ __align__(128) __nv_bfloat16 g_K_hi[BSR * DD], g_K_lo[BSR * DD];
__device__ __align__(128) __nv_bfloat16 g_V_hi[BSR * DD], g_V_lo[BSR * DD];
__device__ __align__(128) __nv_bfloat16 g_Vt_hi[(size_t)BB * DD * SS], g_Vt_lo[(size_t)BB * DD * SS];
__device__ __align__(128) __nv_bfloat16 g_w_hi[(size_t)BB * SS * SS], g_w_lo[(size_t)BB * SS * SS];

// ---------------------------------------------------------------------------
// Helpers
// ---------------------------------------------------------------------------
__device__ __forceinline__ uint32_t smem_to_u32(const void* smem_ptr) {
    uint32_t addr;
    asm("{ .reg .u64 tmp; cvta.to.shared.u64 tmp, %1; cvt.u32.u64 %0, tmp; }"
        : "=r"(addr) : "l"(smem_ptr));
    return addr;
}

__device__ __forceinline__ void cga16(uint32_t dst, const void* src) {
    asm volatile("cp.async.cg.shared.global [%0], [%1], 16;" :: "r"(dst), "l"(src));
}
#define CP_COMMIT() asm volatile("cp.async.commit_group;" ::: "memory")
#define CP_WAIT1()  asm volatile("cp.async.wait_group 1;" ::: "memory")

#define LDSM4(r, a) \
    asm volatile("ldmatrix.sync.aligned.m8n8.x4.shared.b16 {%0,%1,%2,%3}, [%4];" \
        : "=r"((r)[0]), "=r"((r)[1]), "=r"((r)[2]), "=r"((r)[3]) : "r"(a))

__device__ __forceinline__ void mma16816(float* d, const uint32_t* a,
                                         uint32_t b0, uint32_t b1) {
    asm volatile(
        "mma.sync.aligned.m16n8k16.row.col.f32.bf16.bf16.f32 "
        "{%0,%1,%2,%3}, {%4,%5,%6,%7}, {%8,%9}, {%0,%1,%2,%3};"
        : "+f"(d[0]), "+f"(d[1]), "+f"(d[2]), "+f"(d[3])
        : "r"(a[0]), "r"(a[1]), "r"(a[2]), "r"(a[3]), "r"(b0), "r"(b1));
}

__device__ __forceinline__ void split2(float v, __nv_bfloat16& h, __nv_bfloat16& l) {
    h = __float2bfloat16_rn(v);
    l = __float2bfloat16_rn(v - __bfloat162float(h));
}

__device__ __forceinline__ uint32_t packbf(__nv_bfloat16 a, __nv_bfloat16 b) {
    __nv_bfloat162 t = __halves2bfloat162(a, b);
    return *reinterpret_cast<uint32_t*>(&t);
}

// ---------------------------------------------------------------------------
// GEMM core: CTA tile 128(M) x 256(N), 256 threads = 8 warps in a 2x4 grid,
// warp tile 64x64. K-chunk 32, 2-stage cp.async. bf16 hi/lo 3-term split.
// SMEM rows padded to 80B (32 bf16 + 16B) -> conflict-free LDSM + cp.async.
// Stage layout: Ah[128x80] Al[128x80] Bh[256x80] Bl[256x80] = 61440 B.
// ---------------------------------------------------------------------------
#define ROWB    80
#define A_HALF  10240
#define B_HALF  20480
#define ST_BOFF 20480
#define STAGE_B 61440
#define SMEM_BYTES (2 * STAGE_B)   // 122880

__device__ __forceinline__ void gemm_body(
    float acc[4][8][4],
    const __nv_bfloat16* __restrict__ Ah, const __nv_bfloat16* __restrict__ Al, int lda,
    const __nv_bfloat16* __restrict__ Bh, const __nv_bfloat16* __restrict__ Bl, int ldb,
    int ktot)
{
    extern __shared__ char smem[];
    const uint32_t sb = smem_to_u32(smem);
    const int tid = threadIdx.x;
    const int w = tid >> 5, lane = tid & 31;
    const int wm = (w & 1) * 64, wn = (w >> 1) * 64;

    #pragma unroll
    for (int mi = 0; mi < 4; mi++)
        #pragma unroll
        for (int ni = 0; ni < 8; ni++)
            #pragma unroll
            for (int j = 0; j < 4; j++) acc[mi][ni][j] = 0.0f;

    // ldmatrix per-lane source rows/cols
    const int arow = lane & 15, acol = (lane >> 4) * 16;             // A: 16 rows x 2 k-halves
    const int brow = (lane & 7) + ((lane >> 4) << 3);                // B: 8+8 rows
    const int bcol = ((lane >> 3) & 1) * 16;

    const int nch = ktot >> 5;

    auto load_stage = [&](int chunk, int buf) {
        const uint32_t base = sb + buf * STAGE_B;
        const int k0 = chunk << 5;
        // A: 1024 x 16B chunks (hi 512, lo 512)
        #pragma unroll
        for (int i = 0; i < 4; i++) {
            int id = tid + i * 256;
            int half = id >> 9;                 // 0: hi, 1: lo (compile-time per i)
            int r = (id & 511) >> 2, c = id & 3;
            uint32_t dst = base + half * A_HALF + r * ROWB + c * 16;
            const __nv_bfloat16* src = (half ? Al : Ah) + (size_t)r * lda + k0 + c * 8;
            cga16(dst, src);
        }
        // B: 2048 x 16B chunks (hi 1024, lo 1024)
        #pragma unroll
        for (int i = 0; i < 8; i++) {
            int id = tid + i * 256;
            int half = id >> 10;
            int r = (id & 1023) >> 2, c = id & 3;
            uint32_t dst = base + ST_BOFF + half * B_HALF + r * ROWB + c * 16;
            const __nv_bfloat16* src = (half ? Bl : Bh) + (size_t)r * ldb + k0 + c * 8;
            cga16(dst, src);
        }
    };

    load_stage(0, 0);
    CP_COMMIT();

    for (int c = 0; c < nch; c++) {
        if (c + 1 < nch) load_stage(c + 1, (c + 1) & 1);
        CP_COMMIT();
        CP_WAIT1();
        __syncthreads();

        const uint32_t base = sb + (c & 1) * STAGE_B;
        #pragma unroll
        for (int ks = 0; ks < 2; ks++) {
            const int kb = ks * 32;   // byte offset of this k16 step (16 bf16)

            uint32_t AHf[4][4], ALf[4][4];
            #pragma unroll
            for (int mi = 0; mi < 4; mi++) {
                uint32_t a = base + (wm + mi * 16 + arow) * ROWB + kb + acol;
                LDSM4(AHf[mi], a);
                LDSM4(ALf[mi], a + A_HALF);
            }

            #pragma unroll
            for (int nig = 0; nig < 4; nig++) {
                uint32_t ba = base + ST_BOFF + (wn + nig * 16 + brow) * ROWB + kb + bcol;
                uint32_t BHf[4], BLf[4];
                LDSM4(BHf, ba);
                LDSM4(BLf, ba + B_HALF);
                #pragma unroll
                for (int mi = 0; mi < 4; mi++) {
                    float* a0 = acc[mi][2 * nig];
                    float* a1 = acc[mi][2 * nig + 1];
                    mma16816(a0, AHf[mi], BHf[0], BHf[1]);
                    mma16816(a0, AHf[mi], BLf[0], BLf[1]);
                    mma16816(a0, ALf[mi], BHf[0], BHf[1]);
                    mma16816(a1, AHf[mi], BHf[2], BHf[3]);
                    mma16816(a1, AHf[mi], BLf[2], BLf[3]);
                    mma16816(a1, ALf[mi], BHf[2], BHf[3]);
                }
            }
        }
        __syncthreads();
    }
}

// ---------------------------------------------------------------------------
// GEMM kernels
// ---------------------------------------------------------------------------
__global__ void __launch_bounds__(256, 1) qkv_gemm(
    const float* __restrict__ bq, const float* __restrict__ bk,
    const float* __restrict__ bv)
{
    const int z = blockIdx.z;
    const int m0 = blockIdx.y * 128;
    const int n0 = blockIdx.x * 256;
    const __nv_bfloat16* Bh = g_Wt_hi + (size_t)z * DD * DD + (size_t)n0 * DD;
    const __nv_bfloat16* Bl = g_Wt_lo + (size_t)z * DD * DD + (size_t)n0 * DD;
    const float* bias; __nv_bfloat16 *Oh, *Ol;
    if (z == 0)      { bias = bq; Oh = g_Q_hi; Ol = g_Q_lo; }
    else if (z == 1) { bias = bk; Oh = g_K_hi; Ol = g_K_lo; }
    else             { bias = bv; Oh = g_V_hi; Ol = g_V_lo; }

    float acc[4][8][4];
    gemm_body(acc, g_x_hi + (size_t)m0 * DD, g_x_lo + (size_t)m0 * DD, DD,
              Bh, Bl, DD, DD);

    const int tid = threadIdx.x, w = tid >> 5, lane = tid & 31;
    const int wm = (w & 1) * 64, wn = (w >> 1) * 64;
    const int tg = lane >> 2, tig = lane & 3;
    #pragma unroll
    for (int mi = 0; mi < 4; mi++)
        #pragma unroll
        for (int ni = 0; ni < 8; ni++) {
            int row = m0 + wm + mi * 16 + tg;
            int col = n0 + wn + ni * 8 + tig * 2;
            float b0 = bias[col], b1 = bias[col + 1];
            #pragma unroll
            for (int h = 0; h < 2; h++) {
                float v0 = acc[mi][ni][2 * h]     + b0;
                float v1 = acc[mi][ni][2 * h + 1] + b1;
                __nv_bfloat16 h0, l0, h1, l1;
                split2(v0, h0, l0); split2(v1, h1, l1);
                size_t off = (size_t)(row + 8 * h) * DD + col;
                *(uint32_t*)(Oh + off) = packbf(h0, h1);
                *(uint32_t*)(Ol + off) = packbf(l0, l1);
            }
        }
}

__global__ void __launch_bounds__(256, 1) scores_gemm(float* __restrict__ wgt)
{
    const int b = blockIdx.z;
    const int m0 = blockIdx.y * 128;
    const int n0 = blockIdx.x * 256;
    const size_t abase = ((size_t)b * SS + m0) * DD;
    const size_t bbase = ((size_t)b * SS + n0) * DD;

    float acc[4][8][4];
    gemm_body(acc, g_Q_hi + abase, g_Q_lo + abase, DD,
              g_K_hi + bbase, g_K_lo + bbase, DD, DD);

    float* C = wgt + (size_t)b * SS * SS;
    const int tid = threadIdx.x, w = tid >> 5, lane = tid & 31;
    const int wm = (w & 1) * 64, wn = (w >> 1) * 64;
    const int tg = lane >> 2, tig = lane & 3;
    #pragma unroll
    for (int mi = 0; mi < 4; mi++)
        #pragma unroll
        for (int ni = 0; ni < 8; ni++) {
            int row = m0 + wm + mi * 16 + tg;
            int col = n0 + wn + ni * 8 + tig * 2;
            #pragma unroll
            for (int h = 0; h < 2; h++) {
                float2 v;
                v.x = acc[mi][ni][2 * h]     * SCALE;
                v.y = acc[mi][ni][2 * h + 1] * SCALE;
                *(float2*)&C[(size_t)(row + 8 * h) * SS + col] = v;
            }
        }
}

__global__ void __launch_bounds__(256, 1) att_gemm(float* __restrict__ att)
{
    const int b = blockIdx.z;
    const int m0 = blockIdx.y * 128;
    const int n0 = blockIdx.x * 256;
    const size_t abase = (size_t)b * SS * SS + (size_t)m0 * SS;
    const size_t bbase = ((size_t)b * DD + n0) * SS;

    float acc[4][8][4];
    gemm_body(acc, g_w_hi + abase, g_w_lo + abase, SS,
              g_Vt_hi + bbase, g_Vt_lo + bbase, SS, SS);

    float* C = att + (size_t)b * SS * DD;
    const int tid = threadIdx.x, w = tid >> 5, lane = tid & 31;
    const int wm = (w & 1) * 64, wn = (w >> 1) * 64;
    const int tg = lane >> 2, tig = lane & 3;
    #pragma unroll
    for (int mi = 0; mi < 4; mi++)
        #pragma unroll
        for (int ni = 0; ni < 8; ni++) {
            int row = m0 + wm + mi * 16 + tg;
            int col = n0 + wn + ni * 8 + tig * 2;
            #pragma unroll
            for (int h = 0; h < 2; h++) {
                float2 v;
                v.x = acc[mi][ni][2 * h];
                v.y = acc[mi][ni][2 * h + 1];
                *(float2*)&C[(size_t)(row + 8 * h) * DD + col] = v;
            }
        }
}

// ---------------------------------------------------------------------------
// Conversion / transpose kernels
// ---------------------------------------------------------------------------
__global__ __launch_bounds__(256) void conv_x_kernel(const float* __restrict__ x)
{
    size_t i = (size_t)blockIdx.x * 256 + threadIdx.x;   // over BSR*DD/4
    float4 v = ((const float4*)x)[i];
    __nv_bfloat16 h0, l0, h1, l1, h2, l2, h3, l3;
    split2(v.x, h0, l0); split2(v.y, h1, l1);
    split2(v.z, h2, l2); split2(v.w, h3, l3);
    uint2 uh, ul;
    uh.x = packbf(h0, h1); uh.y = packbf(h2, h3);
    ul.x = packbf(l0, l1); ul.y = packbf(l2, l3);
    ((uint2*)g_x_hi)[i] = uh;
    ((uint2*)g_x_lo)[i] = ul;
}

__global__ __launch_bounds__(256) void wt_kernel(
    const float* __restrict__ Wq, const float* __restrict__ Wk,
    const float* __restrict__ Wv)
{
    const int z = blockIdx.z;
    const float* W = (z == 0) ? Wq : (z == 1) ? Wk : Wv;
    __nv_bfloat16* Oh = g_Wt_hi + (size_t)z * DD * DD;
    __nv_bfloat16* Ol = g_Wt_lo + (size_t)z * DD * DD;
    __shared__ float t[32][33];
    const int tx = threadIdx.x & 31, ty = threadIdx.x >> 5;
    const int x = blockIdx.x * 32 + tx;      // n
    const int y0 = blockIdx.y * 32;          // k
    #pragma unroll
    for (int i = 0; i < 4; i++)
        t[ty + i * 8][tx] = W[(size_t)(y0 + ty + i * 8) * DD + x];
    __syncthreads();
    const int xo = y0 + tx;                  // k out
    const int yo0 = blockIdx.x * 32;         // n out
    #pragma unroll
    for (int i = 0; i < 4; i++) {
        float v = t[tx][ty + i * 8];
        __nv_bfloat16 h, l;
        split2(v, h, l);
        size_t o = (size_t)(yo0 + ty + i * 8) * DD + xo;
        Oh[o] = h; Ol[o] = l;
    }
}

__global__ __launch_bounds__(256) void vt_kernel()
{
    const int b = blockIdx.z;
    __shared__ __nv_bfloat16 th[32][33], tl[32][33];
    const int tx = threadIdx.x & 31, ty = threadIdx.x >> 5;
    const int d0 = blockIdx.x * 32, s0 = blockIdx.y * 32;
    #pragma unroll
    for (int i = 0; i < 4; i++) {
        int s = s0 + ty + i * 8;
        size_t gi = (size_t)(b * SS + s) * DD + d0 + tx;
        th[ty + i * 8][tx] = g_V_hi[gi];
        tl[ty + i * 8][tx] = g_V_lo[gi];
    }
    __syncthreads();
    #pragma unroll
    for (int i = 0; i < 4; i++) {
        int d = d0 + ty + i * 8, s = s0 + tx;
        size_t o = ((size_t)b * DD + d) * SS + s;
        g_Vt_hi[o] = th[tx][ty + i * 8];
        g_Vt_lo[o] = tl[tx][ty + i * 8];
    }
}

// ---------------------------------------------------------------------------
// Reductions + softmax + layernorm
// ---------------------------------------------------------------------------
__device__ __forceinline__ float block_reduce_sum(float v, float* sred) {
    #pragma unroll
    for (int o = 16; o > 0; o >>= 1) v += __shfl_xor_sync(0xffffffffu, v, o);
    int wid = threadIdx.x >> 5, lane = threadIdx.x & 31;
    if (lane == 0) sred[wid] = v;
    __syncthreads();
    if (wid == 0) {
        float t = (lane < 8) ? sred[lane] : 0.0f;
        #pragma unroll
        for (int o = 4; o > 0; o >>= 1) t += __shfl_xor_sync(0xffffffffu, t, o);
        if (lane == 0) sred[0] = t;
    }
    __syncthreads();
    float r = sred[0];
    __syncthreads();
    return r;
}

__device__ __forceinline__ float block_reduce_max(float v, float* sred) {
    #pragma unroll
    for (int o = 16; o > 0; o >>= 1) v = fmaxf(v, __shfl_xor_sync(0xffffffffu, v, o));
    int wid = threadIdx.x >> 5, lane = threadIdx.x & 31;
    if (lane == 0) sred[wid] = v;
    __syncthreads();
    if (wid == 0) {
        float t = (lane < 8) ? sred[lane] : -1e30f;
        #pragma unroll
        for (int o = 4; o > 0; o >>= 1) t = fmaxf(t, __shfl_xor_sync(0xffffffffu, t, o));
        if (lane == 0) sred[0] = t;
    }
    __syncthreads();
    float r = sred[0];
    __syncthreads();
    return r;
}

__global__ __launch_bounds__(256) void softmax_kernel(float* __restrict__ w)
{
    const size_t base = (size_t)blockIdx.x * SS;
    float* p = w + base;
    const int tid = threadIdx.x;
    __shared__ float sred[8];

    float v[8];
    float m = -1e30f;
    #pragma unroll
    for (int i = 0; i < 8; i++) {
        v[i] = p[tid + i * 256];
        m = fmaxf(m, v[i]);
    }
    m = block_reduce_max(m, sred);

    float s = 0.0f;
    #pragma unroll
    for (int i = 0; i < 8; i++) {
        v[i] = __expf(v[i] - m);
        s += v[i];
    }
    s = block_reduce_sum(s, sred);
    float inv = 1.0f / s;
    #pragma unroll
    for (int i = 0; i < 8; i++) {
        int idx = tid + i * 256;
        float wv = v[i] * inv;
        p[idx] = wv;
        __nv_bfloat16 h, l;
        split2(wv, h, l);
        g_w_hi[base + idx] = h;
        g_w_lo[base + idx] = l;
    }
}

__global__ __launch_bounds__(256) void ln_kernel(
    const float* __restrict__ x, const float* __restrict__ gamma,
    const float* __restrict__ beta, const float* __restrict__ att,
    float* __restrict__ out1)
{
    const size_t row = blockIdx.x;
    const float* xr = x   + row * DD;
    const float* ar = att + row * DD;
    float* orow = out1 + row * DD;
    const int tid = threadIdx.x;
    __shared__ float sred[8];

    float v[4];
    float s = 0.0f;
    #pragma unroll
    for (int i = 0; i < 4; i++) {
        int c = tid + i * 256;
        v[i] = xr[c] + ar[c];
        s += v[i];
    }
    s = block_reduce_sum(s, sred);
    float mu = s * (1.0f / DD);

    float s2 = 0.0f;
    #pragma unroll
    for (int i = 0; i < 4; i++) {
        float d = v[i] - mu;
        s2 += d * d;
    }
    s2 = block_reduce_sum(s2, sred);
    float rstd = rsqrtf(s2 * (1.0f / DD) + 1e-5f);

    #pragma unroll
    for (int i = 0; i < 4; i++) {
        int c = tid + i * 256;
        orow[c] = (v[i] - mu) * rstd * gamma[c] + beta[c];
    }
}

// ---------------------------------------------------------------------------
// Launch. Inputs: x, Wk, bk, Wq, bq, Wv, bv, gamma, beta_ln.
// Output: [out1 (B*S*D) | att_score (B*S*D) | weight (B*S*S)] fp32.
// ---------------------------------------------------------------------------
extern "C" void kernel_launch(void* const* d_in, const int* in_sizes, int n_in,
                              void* d_out, int out_size)
{
    const float* x     = (const float*)d_in[0];
    const float* Wk    = (const float*)d_in[1];
    const float* bk    = (const float*)d_in[2];
    const float* Wq    = (const float*)d_in[3];
    const float* bq    = (const float*)d_in[4];
    const float* Wv    = (const float*)d_in[5];
    const float* bv    = (const float*)d_in[6];
    const float* gamma = (const float*)d_in[7];
    const float* beta  = (const float*)d_in[8];

    float* out  = (float*)d_out;
    float* out1 = out;                          // [B,S,D]
    float* att  = out + (size_t)BSR * DD;       // [B,S,D]
    float* wgt  = out + (size_t)2 * BSR * DD;   // [B,S,S]

    cudaFuncSetAttribute(qkv_gemm,    cudaFuncAttributeMaxDynamicSharedMemorySize, SMEM_BYTES);
    cudaFuncSetAttribute(scores_gemm, cudaFuncAttributeMaxDynamicSharedMemorySize, SMEM_BYTES);
    cudaFuncSetAttribute(att_gemm,    cudaFuncAttributeMaxDynamicSharedMemorySize, SMEM_BYTES);

    // 1) fp32 -> bf16 hi/lo conversions
    conv_x_kernel<<<BSR * DD / 4 / 256, 256>>>(x);
    wt_kernel<<<dim3(32, 32, 3), 256>>>(Wq, Wk, Wv);
    // 2) QKV projections (tensor cores)
    qkv_gemm<<<dim3(DD / 256, BSR / 128, 3), 256, SMEM_BYTES>>>(bq, bk, bv);
    // 3) V transpose for the att GEMM B operand
    vt_kernel<<<dim3(DD / 32, SS / 32, BB), 256>>>();
    // 4) scores = Q K^T * scale
    scores_gemm<<<dim3(SS / 256, SS / 128, BB), 256, SMEM_BYTES>>>(wgt);
    // 5) softmax (also emits bf16 hi/lo weight copies)
    softmax_kernel<<<BSR, 256>>>(wgt);
    // 6) att = weight @ V
    att_gemm<<<dim3(DD / 256, SS / 128, BB), 256, SMEM_BYTES>>>(att);
    // 7) residual + LayerNorm
    ln_kernel<<<BSR, 256>>>(x, gamma, beta, att, out1);
}

// round 5
// speedup vs baseline: 1.1271x; 1.1271x over previous
#include <cuda_runtime.h>
#include <cuda_bf16.h>
#include <cstdint>
#include <math.h>

#define BB 4
#define SS 2048
#define DD 1024
#define BSR (BB * SS)
#define SCALE (1.0f / 32.0f)

// ---------------------------------------------------------------------------
// Scratch (__device__ globals; no allocation allowed)
// ---------------------------------------------------------------------------
__device__ __align__(128) __nv_bfloat16 g_x_hi[BSR * DD], g_x_lo[BSR * DD];
__device__ __align__(128) __nv_bfloat16 g_Wt_hi[3 * DD * DD], g_Wt_lo[3 * DD * DD];
__device__ __align__(128) __nv_bfloat16 g_Q_hi[BSR * DD], g_Q_lo[BSR * DD];
__device__ __align__(128) __nv_bfloat16 g_K_hi[BSR * DD], g_K_lo[BSR * DD];
__device__ __align__(128) __nv_bfloat16 g_V_hi[BSR * DD], g_V_lo[BSR * DD];
__device__ __align__(128) __nv_bfloat16 g_Vt_hi[(size_t)BB * DD * SS], g_Vt_lo[(size_t)BB * DD * SS];
__device__ __align__(128) __nv_bfloat16 g_w_hi[(size_t)BB * SS * SS], g_w_lo[(size_t)BB * SS * SS];

// ---------------------------------------------------------------------------
// Helpers
// ---------------------------------------------------------------------------
__device__ __forceinline__ uint32_t smem_to_u32(const void* smem_ptr) {
    uint32_t addr;
    asm("{ .reg .u64 tmp; cvta.to.shared.u64 tmp, %1; cvt.u32.u64 %0, tmp; }"
        : "=r"(addr) : "l"(smem_ptr));
    return addr;
}

__device__ __forceinline__ void cga16(uint32_t dst, const void* src) {
    asm volatile("cp.async.cg.shared.global [%0], [%1], 16;" :: "r"(dst), "l"(src));
}
#define CP_COMMIT() asm volatile("cp.async.commit_group;" ::: "memory")
#define CP_WAIT1()  asm volatile("cp.async.wait_group 1;" ::: "memory")

#define LDSM4(r, a) \
    asm volatile("ldmatrix.sync.aligned.m8n8.x4.shared.b16 {%0,%1,%2,%3}, [%4];" \
        : "=r"((r)[0]), "=r"((r)[1]), "=r"((r)[2]), "=r"((r)[3]) : "r"(a))

__device__ __forceinline__ void mma16816(float* d, const uint32_t* a,
                                         uint32_t b0, uint32_t b1) {
    asm volatile(
        "mma.sync.aligned.m16n8k16.row.col.f32.bf16.bf16.f32 "
        "{%0,%1,%2,%3}, {%4,%5,%6,%7}, {%8,%9}, {%0,%1,%2,%3};"
        : "+f"(d[0]), "+f"(d[1]), "+f"(d[2]), "+f"(d[3])
        : "r"(a[0]), "r"(a[1]), "r"(a[2]), "r"(a[3]), "r"(b0), "r"(b1));
}

__device__ __forceinline__ void split2(float v, __nv_bfloat16& h, __nv_bfloat16& l) {
    h = __float2bfloat16_rn(v);
    l = __float2bfloat16_rn(v - __bfloat162float(h));
}

__device__ __forceinline__ uint32_t packbf(__nv_bfloat16 a, __nv_bfloat16 b) {
    __nv_bfloat162 t = __halves2bfloat162(a, b);
    return *reinterpret_cast<uint32_t*>(&t);
}

// ---------------------------------------------------------------------------
// GEMM core: CTA tile 128x128, 256 threads = 8 warps (2 M x 4 N), warp tile
// 64x32. K-chunk 32, 2-stage cp.async (2 CTAs/SM). bf16 hi/lo 3-term split.
// ldmatrix.x4 fragment loads (validated in R4). Rows padded to 80B.
// Stage: Ah[128x80] Al[128x80] Bh[128x80] Bl[128x80] = 40960 B.
// ---------------------------------------------------------------------------
#define ROWB    80
#define TILE_B  10240
#define STAGE_B 40960
#define SMEM_BYTES (2 * STAGE_B)   // 81920

__device__ __forceinline__ void gemm_body(
    float acc[4][4][4],
    const __nv_bfloat16* __restrict__ Ah, const __nv_bfloat16* __restrict__ Al, int lda,
    const __nv_bfloat16* __restrict__ Bh, const __nv_bfloat16* __restrict__ Bl, int ldb,
    int ktot)
{
    extern __shared__ char smem[];
    const uint32_t sb = smem_to_u32(smem);
    const int tid = threadIdx.x;
    const int w = tid >> 5, lane = tid & 31;
    const int wm = (w & 1) * 64, wn = (w >> 1) * 32;

    #pragma unroll
    for (int mi = 0; mi < 4; mi++)
        #pragma unroll
        for (int ni = 0; ni < 4; ni++)
            #pragma unroll
            for (int j = 0; j < 4; j++) acc[mi][ni][j] = 0.0f;

    // ldmatrix lane->address mapping (validated R4)
    const int arow = lane & 15, acol = (lane >> 4) * 16;   // A: (r0-15) x 2 k-halves
    const int brow = (lane & 7) + ((lane >> 4) << 3);      // B: n rows 0-7,0-7,8-15,8-15
    const int bcol = ((lane >> 3) & 1) * 16;               //    k halves 0,16,0,16

    const int id0 = tid, id1 = tid + 256;
    const int r0 = id0 >> 2, c0 = id0 & 3;
    const int r1 = id1 >> 2, c1 = id1 & 3;

    const int nch = ktot >> 5;

    auto load_stage = [&](int chunk, int buf) {
        const uint32_t base = sb + buf * STAGE_B;
        const int k0 = chunk << 5;
        {
            uint32_t so = base + r0 * ROWB + c0 * 16;
            size_t go = (size_t)r0 * lda + k0 + c0 * 8;
            cga16(so, Ah + go);
            cga16(so + TILE_B, Al + go);
        }
        {
            uint32_t so = base + r1 * ROWB + c1 * 16;
            size_t go = (size_t)r1 * lda + k0 + c1 * 8;
            cga16(so, Ah + go);
            cga16(so + TILE_B, Al + go);
        }
        {
            uint32_t so = base + 2 * TILE_B + r0 * ROWB + c0 * 16;
            size_t go = (size_t)r0 * ldb + k0 + c0 * 8;
            cga16(so, Bh + go);
            cga16(so + TILE_B, Bl + go);
        }
        {
            uint32_t so = base + 2 * TILE_B + r1 * ROWB + c1 * 16;
            size_t go = (size_t)r1 * ldb + k0 + c1 * 8;
            cga16(so, Bh + go);
            cga16(so + TILE_B, Bl + go);
        }
    };

    load_stage(0, 0);
    CP_COMMIT();

    for (int c = 0; c < nch; c++) {
        if (c + 1 < nch) load_stage(c + 1, (c + 1) & 1);
        CP_COMMIT();
        CP_WAIT1();
        __syncthreads();

        const uint32_t base = sb + (c & 1) * STAGE_B;
        #pragma unroll
        for (int ks = 0; ks < 2; ks++) {
            const int kb = ks * 32;

            // B fragments for warp's n32: two n16 groups, hi+lo
            uint32_t BHf[2][4], BLf[2][4];
            #pragma unroll
            for (int nig = 0; nig < 2; nig++) {
                uint32_t ba = base + 2 * TILE_B + (wn + nig * 16 + brow) * ROWB + kb + bcol;
                LDSM4(BHf[nig], ba);
                LDSM4(BLf[nig], ba + TILE_B);
            }

            #pragma unroll
            for (int mi = 0; mi < 4; mi++) {
                uint32_t aa = base + (wm + mi * 16 + arow) * ROWB + kb + acol;
                uint32_t AHf[4], ALf[4];
                LDSM4(AHf, aa);
                LDSM4(ALf, aa + TILE_B);
                #pragma unroll
                for (int nig = 0; nig < 2; nig++) {
                    float* a0 = acc[mi][2 * nig];
                    float* a1 = acc[mi][2 * nig + 1];
                    mma16816(a0, AHf, BHf[nig][0], BHf[nig][1]);
                    mma16816(a0, AHf, BLf[nig][0], BLf[nig][1]);
                    mma16816(a0, ALf, BHf[nig][0], BHf[nig][1]);
                    mma16816(a1, AHf, BHf[nig][2], BHf[nig][3]);
                    mma16816(a1, AHf, BLf[nig][2], BLf[nig][3]);
                    mma16816(a1, ALf, BHf[nig][2], BHf[nig][3]);
                }
            }
        }
        __syncthreads();
    }
}

// ---------------------------------------------------------------------------
// GEMM kernels
// ---------------------------------------------------------------------------
__global__ void __launch_bounds__(256, 2) qkv_gemm(
    const float* __restrict__ bq, const float* __restrict__ bk,
    const float* __restrict__ bv)
{
    const int z = blockIdx.z;
    const int m0 = blockIdx.y * 128;
    const int n0 = blockIdx.x * 128;
    const __nv_bfloat16* Bh = g_Wt_hi + (size_t)z * DD * DD + (size_t)n0 * DD;
    const __nv_bfloat16* Bl = g_Wt_lo + (size_t)z * DD * DD + (size_t)n0 * DD;
    const float* bias; __nv_bfloat16 *Oh, *Ol;
    if (z == 0)      { bias = bq; Oh = g_Q_hi; Ol = g_Q_lo; }
    else if (z == 1) { bias = bk; Oh = g_K_hi; Ol = g_K_lo; }
    else             { bias = bv; Oh = g_V_hi; Ol = g_V_lo; }

    float acc[4][4][4];
    gemm_body(acc, g_x_hi + (size_t)m0 * DD, g_x_lo + (size_t)m0 * DD, DD,
              Bh, Bl, DD, DD);

    const int tid = threadIdx.x, w = tid >> 5, lane = tid & 31;
    const int wm = (w & 1) * 64, wn = (w >> 1) * 32;
    const int tg = lane >> 2, tig = lane & 3;
    #pragma unroll
    for (int mi = 0; mi < 4; mi++)
        #pragma unroll
        for (int ni = 0; ni < 4; ni++) {
            int row = m0 + wm + mi * 16 + tg;
            int col = n0 + wn + ni * 8 + tig * 2;
            float b0 = bias[col], b1 = bias[col + 1];
            #pragma unroll
            for (int h = 0; h < 2; h++) {
                float v0 = acc[mi][ni][2 * h]     + b0;
                float v1 = acc[mi][ni][2 * h + 1] + b1;
                __nv_bfloat16 h0, l0, h1, l1;
                split2(v0, h0, l0); split2(v1, h1, l1);
                size_t off = (size_t)(row + 8 * h) * DD + col;
                *(uint32_t*)(Oh + off) = packbf(h0, h1);
                *(uint32_t*)(Ol + off) = packbf(l0, l1);
            }
        }
}

__global__ void __launch_bounds__(256, 2) scores_gemm(float* __restrict__ wgt)
{
    const int b = blockIdx.z;
    const int m0 = blockIdx.y * 128;
    const int n0 = blockIdx.x * 128;
    const size_t abase = ((size_t)b * SS + m0) * DD;
    const size_t bbase = ((size_t)b * SS + n0) * DD;

    float acc[4][4][4];
    gemm_body(acc, g_Q_hi + abase, g_Q_lo + abase, DD,
              g_K_hi + bbase, g_K_lo + bbase, DD, DD);

    float* C = wgt + (size_t)b * SS * SS;
    const int tid = threadIdx.x, w = tid >> 5, lane = tid & 31;
    const int wm = (w & 1) * 64, wn = (w >> 1) * 32;
    const int tg = lane >> 2, tig = lane & 3;
    #pragma unroll
    for (int mi = 0; mi < 4; mi++)
        #pragma unroll
        for (int ni = 0; ni < 4; ni++) {
            int row = m0 + wm + mi * 16 + tg;
            int col = n0 + wn + ni * 8 + tig * 2;
            #pragma unroll
            for (int h = 0; h < 2; h++) {
                float2 v;
                v.x = acc[mi][ni][2 * h]     * SCALE;
                v.y = acc[mi][ni][2 * h + 1] * SCALE;
                *(float2*)&C[(size_t)(row + 8 * h) * SS + col] = v;
            }
        }
}

__global__ void __launch_bounds__(256, 2) att_gemm(float* __restrict__ att)
{
    const int b = blockIdx.z;
    const int m0 = blockIdx.y * 128;
    const int n0 = blockIdx.x * 128;
    const size_t abase = (size_t)b * SS * SS + (size_t)m0 * SS;
    const size_t bbase = ((size_t)b * DD + n0) * SS;

    float acc[4][4][4];
    gemm_body(acc, g_w_hi + abase, g_w_lo + abase, SS,
              g_Vt_hi + bbase, g_Vt_lo + bbase, SS, SS);

    float* C = att + (size_t)b * SS * DD;
    const int tid = threadIdx.x, w = tid >> 5, lane = tid & 31;
    const int wm = (w & 1) * 64, wn = (w >> 1) * 32;
    const int tg = lane >> 2, tig = lane & 3;
    #pragma unroll
    for (int mi = 0; mi < 4; mi++)
        #pragma unroll
        for (int ni = 0; ni < 4; ni++) {
            int row = m0 + wm + mi * 16 + tg;
            int col = n0 + wn + ni * 8 + tig * 2;
            #pragma unroll
            for (int h = 0; h < 2; h++) {
                float2 v;
                v.x = acc[mi][ni][2 * h];
                v.y = acc[mi][ni][2 * h + 1];
                *(float2*)&C[(size_t)(row + 8 * h) * DD + col] = v;
            }
        }
}

// ---------------------------------------------------------------------------
// Conversion / transpose kernels
// ---------------------------------------------------------------------------
__global__ __launch_bounds__(256) void conv_x_kernel(const float* __restrict__ x)
{
    size_t i = (size_t)blockIdx.x * 256 + threadIdx.x;   // over BSR*DD/4
    float4 v = ((const float4*)x)[i];
    __nv_bfloat16 h0, l0, h1, l1, h2, l2, h3, l3;
    split2(v.x, h0, l0); split2(v.y, h1, l1);
    split2(v.z, h2, l2); split2(v.w, h3, l3);
    uint2 uh, ul;
    uh.x = packbf(h0, h1); uh.y = packbf(h2, h3);
    ul.x = packbf(l0, l1); ul.y = packbf(l2, l3);
    ((uint2*)g_x_hi)[i] = uh;
    ((uint2*)g_x_lo)[i] = ul;
}

__global__ __launch_bounds__(256) void wt_kernel(
    const float* __restrict__ Wq, const float* __restrict__ Wk,
    const float* __restrict__ Wv)
{
    const int z = blockIdx.z;
    const float* W = (z == 0) ? Wq : (z == 1) ? Wk : Wv;
    __nv_bfloat16* Oh = g_Wt_hi + (size_t)z * DD * DD;
    __nv_bfloat16* Ol = g_Wt_lo + (size_t)z * DD * DD;
    __shared__ float t[32][33];
    const int tx = threadIdx.x & 31, ty = threadIdx.x >> 5;
    const int x = blockIdx.x * 32 + tx;      // n
    const int y0 = blockIdx.y * 32;          // k
    #pragma unroll
    for (int i = 0; i < 4; i++)
        t[ty + i * 8][tx] = W[(size_t)(y0 + ty + i * 8) * DD + x];
    __syncthreads();
    const int xo = y0 + tx;                  // k out
    const int yo0 = blockIdx.x * 32;         // n out
    #pragma unroll
    for (int i = 0; i < 4; i++) {
        float v = t[tx][ty + i * 8];
        __nv_bfloat16 h, l;
        split2(v, h, l);
        size_t o = (size_t)(yo0 + ty + i * 8) * DD + xo;
        Oh[o] = h; Ol[o] = l;
    }
}

__global__ __launch_bounds__(256) void vt_kernel()
{
    const int b = blockIdx.z;
    __shared__ __nv_bfloat16 th[32][33], tl[32][33];
    const int tx = threadIdx.x & 31, ty = threadIdx.x >> 5;
    const int d0 = blockIdx.x * 32, s0 = blockIdx.y * 32;
    #pragma unroll
    for (int i = 0; i < 4; i++) {
        int s = s0 + ty + i * 8;
        size_t gi = (size_t)(b * SS + s) * DD + d0 + tx;
        th[ty + i * 8][tx] = g_V_hi[gi];
        tl[ty + i * 8][tx] = g_V_lo[gi];
    }
    __syncthreads();
    #pragma unroll
    for (int i = 0; i < 4; i++) {
        int d = d0 + ty + i * 8, s = s0 + tx;
        size_t o = ((size_t)b * DD + d) * SS + s;
        g_Vt_hi[o] = th[tx][ty + i * 8];
        g_Vt_lo[o] = tl[tx][ty + i * 8];
    }
}

// ---------------------------------------------------------------------------
// Reductions + softmax + layernorm
// ---------------------------------------------------------------------------
__device__ __forceinline__ float block_reduce_sum(float v, float* sred) {
    #pragma unroll
    for (int o = 16; o > 0; o >>= 1) v += __shfl_xor_sync(0xffffffffu, v, o);
    int wid = threadIdx.x >> 5, lane = threadIdx.x & 31;
    if (lane == 0) sred[wid] = v;
    __syncthreads();
    if (wid == 0) {
        float t = (lane < 8) ? sred[lane] : 0.0f;
        #pragma unroll
        for (int o = 4; o > 0; o >>= 1) t += __shfl_xor_sync(0xffffffffu, t, o);
        if (lane == 0) sred[0] = t;
    }
    __syncthreads();
    float r = sred[0];
    __syncthreads();
    return r;
}

__device__ __forceinline__ float block_reduce_max(float v, float* sred) {
    #pragma unroll
    for (int o = 16; o > 0; o >>= 1) v = fmaxf(v, __shfl_xor_sync(0xffffffffu, v, o));
    int wid = threadIdx.x >> 5, lane = threadIdx.x & 31;
    if (lane == 0) sred[wid] = v;
    __syncthreads();
    if (wid == 0) {
        float t = (lane < 8) ? sred[lane] : -1e30f;
        #pragma unroll
        for (int o = 4; o > 0; o >>= 1) t = fmaxf(t, __shfl_xor_sync(0xffffffffu, t, o));
        if (lane == 0) sred[0] = t;
    }
    __syncthreads();
    float r = sred[0];
    __syncthreads();
    return r;
}

__global__ __launch_bounds__(256) void softmax_kernel(float* __restrict__ w)
{
    const size_t base = (size_t)blockIdx.x * SS;
    float* p = w + base;
    const int tid = threadIdx.x;
    __shared__ float sred[8];

    float v[8];
    float m = -1e30f;
    #pragma unroll
    for (int i = 0; i < 8; i++) {
        v[i] = p[tid + i * 256];
        m = fmaxf(m, v[i]);
    }
    m = block_reduce_max(m, sred);

    float s = 0.0f;
    #pragma unroll
    for (int i = 0; i < 8; i++) {
        v[i] = __expf(v[i] - m);
        s += v[i];
    }
    s = block_reduce_sum(s, sred);
    float inv = 1.0f / s;
    #pragma unroll
    for (int i = 0; i < 8; i++) {
        int idx = tid + i * 256;
        float wv = v[i] * inv;
        p[idx] = wv;
        __nv_bfloat16 h, l;
        split2(wv, h, l);
        g_w_hi[base + idx] = h;
        g_w_lo[base + idx] = l;
    }
}

__global__ __launch_bounds__(256) void ln_kernel(
    const float* __restrict__ x, const float* __restrict__ gamma,
    const float* __restrict__ beta, const float* __restrict__ att,
    float* __restrict__ out1)
{
    const size_t row = blockIdx.x;
    const float* xr = x   + row * DD;
    const float* ar = att + row * DD;
    float* orow = out1 + row * DD;
    const int tid = threadIdx.x;
    __shared__ float sred[8];

    float v[4];
    float s = 0.0f;
    #pragma unroll
    for (int i = 0; i < 4; i++) {
        int c = tid + i * 256;
        v[i] = xr[c] + ar[c];
        s += v[i];
    }
    s = block_reduce_sum(s, sred);
    float mu = s * (1.0f / DD);

    float s2 = 0.0f;
    #pragma unroll
    for (int i = 0; i < 4; i++) {
        float d = v[i] - mu;
        s2 += d * d;
    }
    s2 = block_reduce_sum(s2, sred);
    float rstd = rsqrtf(s2 * (1.0f / DD) + 1e-5f);

    #pragma unroll
    for (int i = 0; i < 4; i++) {
        int c = tid + i * 256;
        orow[c] = (v[i] - mu) * rstd * gamma[c] + beta[c];
    }
}

// ---------------------------------------------------------------------------
// Launch. Inputs: x, Wk, bk, Wq, bq, Wv, bv, gamma, beta_ln.
// Output: [out1 (B*S*D) | att_score (B*S*D) | weight (B*S*S)] fp32.
// ---------------------------------------------------------------------------
extern "C" void kernel_launch(void* const* d_in, const int* in_sizes, int n_in,
                              void* d_out, int out_size)
{
    const float* x     = (const float*)d_in[0];
    const float* Wk    = (const float*)d_in[1];
    const float* bk    = (const float*)d_in[2];
    const float* Wq    = (const float*)d_in[3];
    const float* bq    = (const float*)d_in[4];
    const float* Wv    = (const float*)d_in[5];
    const float* bv    = (const float*)d_in[6];
    const float* gamma = (const float*)d_in[7];
    const float* beta  = (const float*)d_in[8];

    float* out  = (float*)d_out;
    float* out1 = out;                          // [B,S,D]
    float* att  = out + (size_t)BSR * DD;       // [B,S,D]
    float* wgt  = out + (size_t)2 * BSR * DD;   // [B,S,S]

    cudaFuncSetAttribute(qkv_gemm,    cudaFuncAttributeMaxDynamicSharedMemorySize, SMEM_BYTES);
    cudaFuncSetAttribute(scores_gemm, cudaFuncAttributeMaxDynamicSharedMemorySize, SMEM_BYTES);
    cudaFuncSetAttribute(att_gemm,    cudaFuncAttributeMaxDynamicSharedMemorySize, SMEM_BYTES);

    // 1) fp32 -> bf16 hi/lo conversions
    conv_x_kernel<<<BSR * DD / 4 / 256, 256>>>(x);
    wt_kernel<<<dim3(32, 32, 3), 256>>>(Wq, Wk, Wv);
    // 2) QKV projections (tensor cores)
    qkv_gemm<<<dim3(DD / 128, BSR / 128, 3), 256, SMEM_BYTES>>>(bq, bk, bv);
    // 3) V transpose for the att GEMM B operand
    vt_kernel<<<dim3(DD / 32, SS / 32, BB), 256>>>();
    // 4) scores = Q K^T * scale
    scores_gemm<<<dim3(SS / 128, SS / 128, BB), 256, SMEM_BYTES>>>(wgt);
    // 5) softmax (also emits bf16 hi/lo weight copies)
    softmax_kernel<<<BSR, 256>>>(wgt);
    // 6) att = weight @ V
    att_gemm<<<dim3(DD / 128, SS / 128, BB), 256, SMEM_BYTES>>>(att);
    // 7) residual + LayerNorm
    ln_kernel<<<BSR, 256>>>(x, gamma, beta, att, out1);
}

// round 6
// speedup vs baseline: 1.3061x; 1.1589x over previous
#include <cuda_runtime.h>
#include <cuda_bf16.h>
#include <cstdint>
#include <math.h>

#define BB 4
#define SS 2048
#define DD 1024
#define BSR (BB * SS)
#define SCALE (1.0f / 32.0f)

// ---------------------------------------------------------------------------
// Scratch (__device__ globals; no allocation allowed)
// ---------------------------------------------------------------------------
__device__ __align__(128) __nv_bfloat16 g_x_hi[BSR * DD], g_x_lo[BSR * DD];
__device__ __align__(128) __nv_bfloat16 g_Wt_hi[3 * DD * DD], g_Wt_lo[3 * DD * DD];
__device__ __align__(128) __nv_bfloat16 g_Q_hi[BSR * DD], g_Q_lo[BSR * DD];
__device__ __align__(128) __nv_bfloat16 g_K_hi[BSR * DD], g_K_lo[BSR * DD];
__device__ __align__(128) __nv_bfloat16 g_V_hi[BSR * DD], g_V_lo[BSR * DD];
__device__ __align__(128) __nv_bfloat16 g_Vt_hi[(size_t)BB * DD * SS], g_Vt_lo[(size_t)BB * DD * SS];
__device__ __align__(128) __nv_bfloat16 g_w_hi[(size_t)BB * SS * SS], g_w_lo[(size_t)BB * SS * SS];

// ---------------------------------------------------------------------------
// Helpers
// ---------------------------------------------------------------------------
__device__ __forceinline__ uint32_t smem_to_u32(const void* smem_ptr) {
    uint32_t addr;
    asm("{ .reg .u64 tmp; cvta.to.shared.u64 tmp, %1; cvt.u32.u64 %0, tmp; }"
        : "=r"(addr) : "l"(smem_ptr));
    return addr;
}

__device__ __forceinline__ void cga16(uint32_t dst, const void* src) {
    asm volatile("cp.async.cg.shared.global [%0], [%1], 16;" :: "r"(dst), "l"(src));
}
#define CP_COMMIT() asm volatile("cp.async.commit_group;" ::: "memory")
#define CP_WAIT1()  asm volatile("cp.async.wait_group 1;" ::: "memory")

#define LDSM4(r, a) \
    asm volatile("ldmatrix.sync.aligned.m8n8.x4.shared.b16 {%0,%1,%2,%3}, [%4];" \
        : "=r"((r)[0]), "=r"((r)[1]), "=r"((r)[2]), "=r"((r)[3]) : "r"(a))

__device__ __forceinline__ void mma16816(float* d, const uint32_t* a,
                                         uint32_t b0, uint32_t b1) {
    asm volatile(
        "mma.sync.aligned.m16n8k16.row.col.f32.bf16.bf16.f32 "
        "{%0,%1,%2,%3}, {%4,%5,%6,%7}, {%8,%9}, {%0,%1,%2,%3};"
        : "+f"(d[0]), "+f"(d[1]), "+f"(d[2]), "+f"(d[3])
        : "r"(a[0]), "r"(a[1]), "r"(a[2]), "r"(a[3]), "r"(b0), "r"(b1));
}

__device__ __forceinline__ void split2(float v, __nv_bfloat16& h, __nv_bfloat16& l) {
    h = __float2bfloat16_rn(v);
    l = __float2bfloat16_rn(v - __bfloat162float(h));
}

__device__ __forceinline__ uint32_t packbf(__nv_bfloat16 a, __nv_bfloat16 b) {
    __nv_bfloat162 t = __halves2bfloat162(a, b);
    return *reinterpret_cast<uint32_t*>(&t);
}

// Packed 64B-row tile with XOR-16B swizzle: physical 16B column = c ^ ((row>>1)&3).
// Conflict-free for cp.async 16B stores and all ldmatrix phases (verified per-phase).
__device__ __forceinline__ uint32_t sw64(int row, int cbyte) {
    return (uint32_t)(row * 64 + ((((cbyte >> 4) ^ ((row >> 1) & 3)) << 4) | (cbyte & 15)));
}

// ---------------------------------------------------------------------------
// GEMM core: CTA tile 128x128, 8 warps (2M x 4N), warp tile 64x32, K-chunk 32.
// 3-stage cp.async pipeline, ONE __syncthreads per chunk. bf16 hi/lo 3-term.
// Stage: Ah[8K] Al[8K] Bh[8K] Bl[8K] = 32768 B. 3 stages, 2 CTAs/SM.
// ---------------------------------------------------------------------------
#define T_AL  8192
#define T_BH  16384
#define T_BL  24576
#define STAGE_B 32768
#define NSTAGE  3
#define SMEM_BYTES (NSTAGE * STAGE_B)   // 98304

__device__ __forceinline__ void gemm_body(
    float acc[4][4][4],
    const __nv_bfloat16* __restrict__ Ah, const __nv_bfloat16* __restrict__ Al, int lda,
    const __nv_bfloat16* __restrict__ Bh, const __nv_bfloat16* __restrict__ Bl, int ldb,
    int ktot)
{
    extern __shared__ char smem[];
    const uint32_t sb = smem_to_u32(smem);
    const int tid = threadIdx.x;
    const int w = tid >> 5, lane = tid & 31;
    const int wm = (w & 1) * 64, wn = (w >> 1) * 32;

    #pragma unroll
    for (int mi = 0; mi < 4; mi++)
        #pragma unroll
        for (int ni = 0; ni < 4; ni++)
            #pragma unroll
            for (int j = 0; j < 4; j++) acc[mi][ni][j] = 0.0f;

    // ldmatrix lane -> (row, 16B col) mapping (validated R4/R5)
    const int arow = lane & 15, acol = (lane >> 4) * 16;
    const int brow = (lane & 7) + ((lane >> 4) << 3);
    const int bcol = ((lane >> 3) & 1) * 16;

    // loader indices: 2 rows per thread per tile (r0, r0+64), 16B col c0
    const int r0 = tid >> 2, c0 = (tid & 3) * 16;
    const uint32_t o0 = sw64(r0, c0), o1 = sw64(r0 + 64, c0);

    const int nch = ktot >> 5;

    auto load_stage = [&](int chunk, int buf) {
        const uint32_t base = sb + buf * STAGE_B;
        const int k0 = (chunk << 5) + (c0 >> 1);      // bf16 element offset (c0/2 elems)
        const size_t a0 = (size_t)r0 * lda + k0, a1 = (size_t)(r0 + 64) * lda + k0;
        const size_t b0 = (size_t)r0 * ldb + k0, b1 = (size_t)(r0 + 64) * ldb + k0;
        cga16(base + o0, Ah + a0);          cga16(base + o1, Ah + a1);
        cga16(base + T_AL + o0, Al + a0);   cga16(base + T_AL + o1, Al + a1);
        cga16(base + T_BH + o0, Bh + b0);   cga16(base + T_BH + o1, Bh + b1);
        cga16(base + T_BL + o0, Bl + b0);   cga16(base + T_BL + o1, Bl + b1);
    };

    load_stage(0, 0); CP_COMMIT();
    load_stage(1, 1); CP_COMMIT();

    int buf = 0, nbuf = 2;
    for (int c = 0; c < nch; c++) {
        CP_WAIT1();
        __syncthreads();
        if (c + 2 < nch) load_stage(c + 2, nbuf);
        CP_COMMIT();
        if (++nbuf == NSTAGE) nbuf = 0;

        const uint32_t base = sb + buf * STAGE_B;
        if (++buf == NSTAGE) buf = 0;

        #pragma unroll
        for (int ks = 0; ks < 2; ks++) {
            const int kb = ks * 32;

            uint32_t BHf[2][4], BLf[2][4];
            #pragma unroll
            for (int nig = 0; nig < 2; nig++) {
                uint32_t ba = base + T_BH + sw64(wn + nig * 16 + brow, kb + bcol);
                LDSM4(BHf[nig], ba);
                LDSM4(BLf[nig], ba + (T_BL - T_BH));
            }

            #pragma unroll
            for (int mi = 0; mi < 4; mi++) {
                uint32_t aa = base + sw64(wm + mi * 16 + arow, kb + acol);
                uint32_t AHf[4], ALf[4];
                LDSM4(AHf, aa);
                LDSM4(ALf, aa + T_AL);
                #pragma unroll
                for (int nig = 0; nig < 2; nig++) {
                    float* d0 = acc[mi][2 * nig];
                    float* d1 = acc[mi][2 * nig + 1];
                    mma16816(d0, AHf, BHf[nig][0], BHf[nig][1]);
                    mma16816(d0, AHf, BLf[nig][0], BLf[nig][1]);
                    mma16816(d0, ALf, BHf[nig][0], BHf[nig][1]);
                    mma16816(d1, AHf, BHf[nig][2], BHf[nig][3]);
                    mma16816(d1, AHf, BLf[nig][2], BLf[nig][3]);
                    mma16816(d1, ALf, BHf[nig][2], BHf[nig][3]);
                }
            }
        }
        __syncthreads();
    }
}

// ---------------------------------------------------------------------------
// GEMM kernels
// ---------------------------------------------------------------------------
__global__ void __launch_bounds__(256, 2) qkv_gemm(
    const float* __restrict__ bq, const float* __restrict__ bk,
    const float* __restrict__ bv)
{
    const int z = blockIdx.z;
    const int m0 = blockIdx.y * 128;
    const int n0 = blockIdx.x * 128;
    const __nv_bfloat16* Bh = g_Wt_hi + (size_t)z * DD * DD + (size_t)n0 * DD;
    const __nv_bfloat16* Bl = g_Wt_lo + (size_t)z * DD * DD + (size_t)n0 * DD;
    const float* bias; __nv_bfloat16 *Oh, *Ol;
    if (z == 0)      { bias = bq; Oh = g_Q_hi; Ol = g_Q_lo; }
    else if (z == 1) { bias = bk; Oh = g_K_hi; Ol = g_K_lo; }
    else             { bias = bv; Oh = g_V_hi; Ol = g_V_lo; }

    float acc[4][4][4];
    gemm_body(acc, g_x_hi + (size_t)m0 * DD, g_x_lo + (size_t)m0 * DD, DD,
              Bh, Bl, DD, DD);

    const int tid = threadIdx.x, w = tid >> 5, lane = tid & 31;
    const int wm = (w & 1) * 64, wn = (w >> 1) * 32;
    const int tg = lane >> 2, tig = lane & 3;
    #pragma unroll
    for (int mi = 0; mi < 4; mi++)
        #pragma unroll
        for (int ni = 0; ni < 4; ni++) {
            int row = m0 + wm + mi * 16 + tg;
            int col = n0 + wn + ni * 8 + tig * 2;
            float b0 = bias[col], b1 = bias[col + 1];
            #pragma unroll
            for (int h = 0; h < 2; h++) {
                float v0 = acc[mi][ni][2 * h]     + b0;
                float v1 = acc[mi][ni][2 * h + 1] + b1;
                __nv_bfloat16 h0, l0, h1, l1;
                split2(v0, h0, l0); split2(v1, h1, l1);
                size_t off = (size_t)(row + 8 * h) * DD + col;
                *(uint32_t*)(Oh + off) = packbf(h0, h1);
                *(uint32_t*)(Ol + off) = packbf(l0, l1);
            }
        }
}

__global__ void __launch_bounds__(256, 2) scores_gemm(float* __restrict__ wgt)
{
    const int b = blockIdx.z;
    const int m0 = blockIdx.y * 128;
    const int n0 = blockIdx.x * 128;
    const size_t abase = ((size_t)b * SS + m0) * DD;
    const size_t bbase = ((size_t)b * SS + n0) * DD;

    float acc[4][4][4];
    gemm_body(acc, g_Q_hi + abase, g_Q_lo + abase, DD,
              g_K_hi + bbase, g_K_lo + bbase, DD, DD);

    float* C = wgt + (size_t)b * SS * SS;
    const int tid = threadIdx.x, w = tid >> 5, lane = tid & 31;
    const int wm = (w & 1) * 64, wn = (w >> 1) * 32;
    const int tg = lane >> 2, tig = lane & 3;
    #pragma unroll
    for (int mi = 0; mi < 4; mi++)
        #pragma unroll
        for (int ni = 0; ni < 4; ni++) {
            int row = m0 + wm + mi * 16 + tg;
            int col = n0 + wn + ni * 8 + tig * 2;
            #pragma unroll
            for (int h = 0; h < 2; h++) {
                float2 v;
                v.x = acc[mi][ni][2 * h]     * SCALE;
                v.y = acc[mi][ni][2 * h + 1] * SCALE;
                *(float2*)&C[(size_t)(row + 8 * h) * SS + col] = v;
            }
        }
}

__global__ void __launch_bounds__(256, 2) att_gemm(float* __restrict__ att)
{
    const int b = blockIdx.z;
    const int m0 = blockIdx.y * 128;
    const int n0 = blockIdx.x * 128;
    const size_t abase = (size_t)b * SS * SS + (size_t)m0 * SS;
    const size_t bbase = ((size_t)b * DD + n0) * SS;

    float acc[4][4][4];
    gemm_body(acc, g_w_hi + abase, g_w_lo + abase, SS,
              g_Vt_hi + bbase, g_Vt_lo + bbase, SS, SS);

    float* C = att + (size_t)b * SS * DD;
    const int tid = threadIdx.x, w = tid >> 5, lane = tid & 31;
    const int wm = (w & 1) * 64, wn = (w >> 1) * 32;
    const int tg = lane >> 2, tig = lane & 3;
    #pragma unroll
    for (int mi = 0; mi < 4; mi++)
        #pragma unroll
        for (int ni = 0; ni < 4; ni++) {
            int row = m0 + wm + mi * 16 + tg;
            int col = n0 + wn + ni * 8 + tig * 2;
            #pragma unroll
            for (int h = 0; h < 2; h++) {
                float2 v;
                v.x = acc[mi][ni][2 * h];
                v.y = acc[mi][ni][2 * h + 1];
                *(float2*)&C[(size_t)(row + 8 * h) * DD + col] = v;
            }
        }
}

// ---------------------------------------------------------------------------
// Conversion / transpose kernels
// ---------------------------------------------------------------------------
__global__ __launch_bounds__(256) void conv_x_kernel(const float* __restrict__ x)
{
    size_t i = (size_t)blockIdx.x * 256 + threadIdx.x;   // over BSR*DD/4
    float4 v = ((const float4*)x)[i];
    __nv_bfloat16 h0, l0, h1, l1, h2, l2, h3, l3;
    split2(v.x, h0, l0); split2(v.y, h1, l1);
    split2(v.z, h2, l2); split2(v.w, h3, l3);
    uint2 uh, ul;
    uh.x = packbf(h0, h1); uh.y = packbf(h2, h3);
    ul.x = packbf(l0, l1); ul.y = packbf(l2, l3);
    ((uint2*)g_x_hi)[i] = uh;
    ((uint2*)g_x_lo)[i] = ul;
}

__global__ __launch_bounds__(256) void wt_kernel(
    const float* __restrict__ Wq, const float* __restrict__ Wk,
    const float* __restrict__ Wv)
{
    const int z = blockIdx.z;
    const float* W = (z == 0) ? Wq : (z == 1) ? Wk : Wv;
    __nv_bfloat16* Oh = g_Wt_hi + (size_t)z * DD * DD;
    __nv_bfloat16* Ol = g_Wt_lo + (size_t)z * DD * DD;
    __shared__ float t[32][33];
    const int tx = threadIdx.x & 31, ty = threadIdx.x >> 5;
    const int x = blockIdx.x * 32 + tx;      // n
    const int y0 = blockIdx.y * 32;          // k
    #pragma unroll
    for (int i = 0; i < 4; i++)
        t[ty + i * 8][tx] = W[(size_t)(y0 + ty + i * 8) * DD + x];
    __syncthreads();
    const int xo = y0 + tx;                  // k out
    const int yo0 = blockIdx.x * 32;         // n out
    #pragma unroll
    for (int i = 0; i < 4; i++) {
        float v = t[tx][ty + i * 8];
        __nv_bfloat16 h, l;
        split2(v, h, l);
        size_t o = (size_t)(yo0 + ty + i * 8) * DD + xo;
        Oh[o] = h; Ol[o] = l;
    }
}

__global__ __launch_bounds__(256) void vt_kernel()
{
    const int b = blockIdx.z;
    __shared__ __nv_bfloat16 th[32][33], tl[32][33];
    const int tx = threadIdx.x & 31, ty = threadIdx.x >> 5;
    const int d0 = blockIdx.x * 32, s0 = blockIdx.y * 32;
    #pragma unroll
    for (int i = 0; i < 4; i++) {
        int s = s0 + ty + i * 8;
        size_t gi = (size_t)(b * SS + s) * DD + d0 + tx;
        th[ty + i * 8][tx] = g_V_hi[gi];
        tl[ty + i * 8][tx] = g_V_lo[gi];
    }
    __syncthreads();
    #pragma unroll
    for (int i = 0; i < 4; i++) {
        int d = d0 + ty + i * 8, s = s0 + tx;
        size_t o = ((size_t)b * DD + d) * SS + s;
        g_Vt_hi[o] = th[tx][ty + i * 8];
        g_Vt_lo[o] = tl[tx][ty + i * 8];
    }
}

// ---------------------------------------------------------------------------
// Reductions + softmax + layernorm
// ---------------------------------------------------------------------------
__device__ __forceinline__ float block_reduce_sum(float v, float* sred) {
    #pragma unroll
    for (int o = 16; o > 0; o >>= 1) v += __shfl_xor_sync(0xffffffffu, v, o);
    int wid = threadIdx.x >> 5, lane = threadIdx.x & 31;
    if (lane == 0) sred[wid] = v;
    __syncthreads();
    if (wid == 0) {
        float t = (lane < 8) ? sred[lane] : 0.0f;
        #pragma unroll
        for (int o = 4; o > 0; o >>= 1) t += __shfl_xor_sync(0xffffffffu, t, o);
        if (lane == 0) sred[0] = t;
    }
    __syncthreads();
    float r = sred[0];
    __syncthreads();
    return r;
}

__device__ __forceinline__ float block_reduce_max(float v, float* sred) {
    #pragma unroll
    for (int o = 16; o > 0; o >>= 1) v = fmaxf(v, __shfl_xor_sync(0xffffffffu, v, o));
    int wid = threadIdx.x >> 5, lane = threadIdx.x & 31;
    if (lane == 0) sred[wid] = v;
    __syncthreads();
    if (wid == 0) {
        float t = (lane < 8) ? sred[lane] : -1e30f;
        #pragma unroll
        for (int o = 4; o > 0; o >>= 1) t = fmaxf(t, __shfl_xor_sync(0xffffffffu, t, o));
        if (lane == 0) sred[0] = t;
    }
    __syncthreads();
    float r = sred[0];
    __syncthreads();
    return r;
}

__global__ __launch_bounds__(256) void softmax_kernel(float* __restrict__ w)
{
    const size_t base = (size_t)blockIdx.x * SS;
    float* p = w + base;
    const int tid = threadIdx.x;
    __shared__ float sred[8];

    float v[8];
    float m = -1e30f;
    #pragma unroll
    for (int i = 0; i < 8; i++) {
        v[i] = p[tid + i * 256];
        m = fmaxf(m, v[i]);
    }
    m = block_reduce_max(m, sred);

    float s = 0.0f;
    #pragma unroll
    for (int i = 0; i < 8; i++) {
        v[i] = __expf(v[i] - m);
        s += v[i];
    }
    s = block_reduce_sum(s, sred);
    float inv = 1.0f / s;
    #pragma unroll
    for (int i = 0; i < 8; i++) {
        int idx = tid + i * 256;
        float wv = v[i] * inv;
        p[idx] = wv;
        __nv_bfloat16 h, l;
        split2(wv, h, l);
        g_w_hi[base + idx] = h;
        g_w_lo[base + idx] = l;
    }
}

__global__ __launch_bounds__(256) void ln_kernel(
    const float* __restrict__ x, const float* __restrict__ gamma,
    const float* __restrict__ beta, const float* __restrict__ att,
    float* __restrict__ out1)
{
    const size_t row = blockIdx.x;
    const float* xr = x   + row * DD;
    const float* ar = att + row * DD;
    float* orow = out1 + row * DD;
    const int tid = threadIdx.x;
    __shared__ float sred[8];

    float v[4];
    float s = 0.0f;
    #pragma unroll
    for (int i = 0; i < 4; i++) {
        int c = tid + i * 256;
        v[i] = xr[c] + ar[c];
        s += v[i];
    }
    s = block_reduce_sum(s, sred);
    float mu = s * (1.0f / DD);

    float s2 = 0.0f;
    #pragma unroll
    for (int i = 0; i < 4; i++) {
        float d = v[i] - mu;
        s2 += d * d;
    }
    s2 = block_reduce_sum(s2, sred);
    float rstd = rsqrtf(s2 * (1.0f / DD) + 1e-5f);

    #pragma unroll
    for (int i = 0; i < 4; i++) {
        int c = tid + i * 256;
        orow[c] = (v[i] - mu) * rstd * gamma[c] + beta[c];
    }
}

// ---------------------------------------------------------------------------
// Launch. Inputs: x, Wk, bk, Wq, bq, Wv, bv, gamma, beta_ln.
// Output: [out1 (B*S*D) | att_score (B*S*D) | weight (B*S*S)] fp32.
// NOTE: scores_gemm is deliberately the 4th launch so ncu (-s 3 -c 1)
// profiles a GEMM kernel instead of vt_kernel.
// ---------------------------------------------------------------------------
extern "C" void kernel_launch(void* const* d_in, const int* in_sizes, int n_in,
                              void* d_out, int out_size)
{
    const float* x     = (const float*)d_in[0];
    const float* Wk    = (const float*)d_in[1];
    const float* bk    = (const float*)d_in[2];
    const float* Wq    = (const float*)d_in[3];
    const float* bq    = (const float*)d_in[4];
    const float* Wv    = (const float*)d_in[5];
    const float* bv    = (const float*)d_in[6];
    const float* gamma = (const float*)d_in[7];
    const float* beta  = (const float*)d_in[8];

    float* out  = (float*)d_out;
    float* out1 = out;                          // [B,S,D]
    float* att  = out + (size_t)BSR * DD;       // [B,S,D]
    float* wgt  = out + (size_t)2 * BSR * DD;   // [B,S,S]

    cudaFuncSetAttribute(qkv_gemm,    cudaFuncAttributeMaxDynamicSharedMemorySize, SMEM_BYTES);
    cudaFuncSetAttribute(scores_gemm, cudaFuncAttributeMaxDynamicSharedMemorySize, SMEM_BYTES);
    cudaFuncSetAttribute(att_gemm,    cudaFuncAttributeMaxDynamicSharedMemorySize, SMEM_BYTES);

    // 1) fp32 -> bf16 hi/lo conversions
    conv_x_kernel<<<BSR * DD / 4 / 256, 256>>>(x);
    wt_kernel<<<dim3(32, 32, 3), 256>>>(Wq, Wk, Wv);
    // 2) QKV projections (tensor cores)
    qkv_gemm<<<dim3(DD / 128, BSR / 128, 3), 256, SMEM_BYTES>>>(bq, bk, bv);
    // 3) scores = Q K^T * scale   (4th launch -> profiled by ncu)
    scores_gemm<<<dim3(SS / 128, SS / 128, BB), 256, SMEM_BYTES>>>(wgt);
    // 4) V transpose for att GEMM B operand
    vt_kernel<<<dim3(DD / 32, SS / 32, BB), 256>>>();
    // 5) softmax (also emits bf16 hi/lo weight copies)
    softmax_kernel<<<BSR, 256>>>(wgt);
    // 6) att = weight @ V
    att_gemm<<<dim3(DD / 128, SS / 128, BB), 256, SMEM_BYTES>>>(att);
    // 7) residual + LayerNorm
    ln_kernel<<<BSR, 256>>>(x, gamma, beta, att, out1);
}